// round 1
// baseline (speedup 1.0000x reference)
#include <cuda_runtime.h>
#include <math.h>

#define T_SEQ  4096
#define D_MODEL 1024
#define NH      16
#define CH      64

// ---------------- scratch (device globals; no allocation allowed) ----------
__device__ float g_Q[NH * T_SEQ * CH];     // [h][t][c], rope applied
__device__ float g_K[NH * T_SEQ * CH];     // [h][t][c], rope applied
__device__ float g_V[NH * T_SEQ * CH];     // [h][t][c]
__device__ float g_att[T_SEQ * D_MODEL];   // [t][h*64+c]
__device__ float g_sin[T_SEQ * 32];
__device__ float g_cos[T_SEQ * 32];

// ---------------- RoPE sin/cos table ---------------------------------------
__global__ void rope_table_kernel() {
    int t = blockIdx.x;
    int p = threadIdx.x;                       // pair index 0..31
    double inv = pow(10000.0, -(double)(2 * p) / 64.0);
    float ang = (float)t * (float)inv;
    float s, c;
    sincosf(ang, &s, &c);
    g_sin[t * 32 + p] = s;
    g_cos[t * 32 + p] = c;
}

// ---------------- QKV GEMM (+fused RoPE epilogue) ---------------------------
// C[m][n] = sum_k x[m][k] * Wqkv[n][k];  M=4096, N=3072, K=1024
__global__ __launch_bounds__(256) void qkv_rope_gemm(
    const float* __restrict__ A, const float* __restrict__ B) {
    __shared__ float As[8][128];
    __shared__ float Bs[8][128];
    int tid = threadIdx.x;
    int bm = blockIdx.y, bn = blockIdx.x;
    int tr = tid >> 4, tc = tid & 15;          // 16x16 thread grid, 8x8 microtile
    int lr = tid >> 1, lk = (tid & 1) * 4;     // load coords

    const float* Ap = A + (size_t)(bm * 128 + lr) * D_MODEL + lk;
    const float* Bp = B + (size_t)(bn * 128 + lr) * D_MODEL + lk;

    float acc[8][8];
#pragma unroll
    for (int i = 0; i < 8; i++)
#pragma unroll
        for (int j = 0; j < 8; j++) acc[i][j] = 0.f;

    for (int k0 = 0; k0 < D_MODEL; k0 += 8) {
        float4 a = *(const float4*)(Ap + k0);
        float4 b = *(const float4*)(Bp + k0);
        As[lk + 0][lr] = a.x; As[lk + 1][lr] = a.y;
        As[lk + 2][lr] = a.z; As[lk + 3][lr] = a.w;
        Bs[lk + 0][lr] = b.x; Bs[lk + 1][lr] = b.y;
        Bs[lk + 2][lr] = b.z; Bs[lk + 3][lr] = b.w;
        __syncthreads();
#pragma unroll
        for (int kk = 0; kk < 8; kk++) {
            float ar[8], br[8];
            *(float4*)&ar[0] = *(const float4*)&As[kk][tr * 8];
            *(float4*)&ar[4] = *(const float4*)&As[kk][tr * 8 + 4];
            *(float4*)&br[0] = *(const float4*)&Bs[kk][tc * 8];
            *(float4*)&br[4] = *(const float4*)&Bs[kk][tc * 8 + 4];
#pragma unroll
            for (int i = 0; i < 8; i++)
#pragma unroll
                for (int j = 0; j < 8; j++)
                    acc[i][j] = fmaf(ar[i], br[j], acc[i][j]);
        }
        __syncthreads();
    }

    // epilogue: split q/k/v, apply rope to q,k, scatter to [h][t][c]
    int m0 = bm * 128 + tr * 8;
    int n0 = bn * 128 + tc * 8;
    int mat = n0 >> 10;                // 0=q, 1=k, 2=v (tile never crosses)
    int j1024 = n0 & 1023;
    int h = j1024 >> 6;
    int cbase = j1024 & 63;            // multiple of 8, stays within head
    float* dst = (mat == 0) ? g_Q : (mat == 1 ? g_K : g_V);

#pragma unroll
    for (int i = 0; i < 8; i++) {
        int t = m0 + i;
        size_t base = (size_t)h * T_SEQ * CH + (size_t)t * CH + cbase;
        if (mat == 2) {
#pragma unroll
            for (int j = 0; j < 8; j++) dst[base + j] = acc[i][j];
        } else {
#pragma unroll
            for (int jp = 0; jp < 4; jp++) {
                int p = (cbase + jp * 2) >> 1;
                float sn = g_sin[t * 32 + p];
                float cs = g_cos[t * 32 + p];
                float xe = acc[i][jp * 2];
                float xo = acc[i][jp * 2 + 1];
                dst[base + jp * 2]     = xe * cs - xo * sn;
                dst[base + jp * 2 + 1] = xo * cs + xe * sn;
            }
        }
    }
}

// ---------------- Flash attention (fp32, online softmax) -------------------
#define SMS 68                                  // padded smem row stride
#define FLASH_SMEM (4 * 64 * SMS * 4)

__global__ __launch_bounds__(256) void flash_kernel() {
    extern __shared__ float sm[];
    float* Qs  = sm;                  // [r][c]  64 x SMS
    float* Kts = sm + 64 * SMS;       // [c][j]  (K transposed)
    float* Vs  = sm + 2 * 64 * SMS;   // [j][c]
    float* Ps  = sm + 3 * 64 * SMS;   // [r][j]

    int h  = blockIdx.y;
    int qi = 63 - blockIdx.x;         // heavy tiles first
    int tid = threadIdx.x;
    int ty = tid >> 4, tx = tid & 15;
    int r0 = ty * 4, c0o = tx * 4;

    const float* Qg = g_Q + (size_t)h * T_SEQ * CH;
    const float* Kg = g_K + (size_t)h * T_SEQ * CH;
    const float* Vg = g_V + (size_t)h * T_SEQ * CH;

    // load Q tile
    for (int i = tid; i < 64 * 16; i += 256) {
        int r = i >> 4, c4 = (i & 15) * 4;
        float4 q = *(const float4*)(Qg + (size_t)(qi * 64 + r) * 64 + c4);
        Qs[r * SMS + c4 + 0] = q.x; Qs[r * SMS + c4 + 1] = q.y;
        Qs[r * SMS + c4 + 2] = q.z; Qs[r * SMS + c4 + 3] = q.w;
    }

    float m_i[4], l_i[4], o[4][4];
#pragma unroll
    for (int ii = 0; ii < 4; ii++) {
        m_i[ii] = -1e30f; l_i[ii] = 0.f;
#pragma unroll
        for (int cc = 0; cc < 4; cc++) o[ii][cc] = 0.f;
    }

    for (int kt = 0; kt <= qi; kt++) {
        __syncthreads();   // prev PV reads done (also covers Q load on iter 0)
        // load K (transposed) and V tiles
        for (int i = tid; i < 64 * 16; i += 256) {
            int r = i >> 4, c4 = (i & 15) * 4;
            float4 kk = *(const float4*)(Kg + (size_t)(kt * 64 + r) * 64 + c4);
            Kts[(c4 + 0) * SMS + r] = kk.x; Kts[(c4 + 1) * SMS + r] = kk.y;
            Kts[(c4 + 2) * SMS + r] = kk.z; Kts[(c4 + 3) * SMS + r] = kk.w;
            float4 vv = *(const float4*)(Vg + (size_t)(kt * 64 + r) * 64 + c4);
            Vs[r * SMS + c4 + 0] = vv.x; Vs[r * SMS + c4 + 1] = vv.y;
            Vs[r * SMS + c4 + 2] = vv.z; Vs[r * SMS + c4 + 3] = vv.w;
        }
        __syncthreads();

        // S = Q K^T for this thread's 4x4
        float s[4][4];
#pragma unroll
        for (int ii = 0; ii < 4; ii++)
#pragma unroll
            for (int jj = 0; jj < 4; jj++) s[ii][jj] = 0.f;

        for (int c = 0; c < 64; c += 4) {
            float4 qv[4], kv[4];
#pragma unroll
            for (int ii = 0; ii < 4; ii++)
                qv[ii] = *(const float4*)&Qs[(r0 + ii) * SMS + c];
#pragma unroll
            for (int cc = 0; cc < 4; cc++)
                kv[cc] = *(const float4*)&Kts[(c + cc) * SMS + c0o];
            const float* qf = (const float*)qv;
            const float* kf = (const float*)kv;
#pragma unroll
            for (int ii = 0; ii < 4; ii++)
#pragma unroll
                for (int cc = 0; cc < 4; cc++) {
                    float q = qf[ii * 4 + cc];
#pragma unroll
                    for (int jj = 0; jj < 4; jj++)
                        s[ii][jj] = fmaf(q, kf[cc * 4 + jj], s[ii][jj]);
                }
        }

        bool diag = (kt == qi);
#pragma unroll
        for (int ii = 0; ii < 4; ii++)
#pragma unroll
            for (int jj = 0; jj < 4; jj++) {
                float v = s[ii][jj] * 0.125f;   // 1/sqrt(64)
                if (diag && (c0o + jj > r0 + ii)) v = -1e30f;
                s[ii][jj] = v;
            }

        // online softmax per row (16 lanes share a row)
#pragma unroll
        for (int ii = 0; ii < 4; ii++) {
            float rmax = fmaxf(fmaxf(s[ii][0], s[ii][1]), fmaxf(s[ii][2], s[ii][3]));
#pragma unroll
            for (int off = 8; off >= 1; off >>= 1)
                rmax = fmaxf(rmax, __shfl_xor_sync(0xffffffffu, rmax, off, 16));
            float mnew = fmaxf(m_i[ii], rmax);
            float alpha = __expf(m_i[ii] - mnew);
            float p0 = __expf(s[ii][0] - mnew);
            float p1 = __expf(s[ii][1] - mnew);
            float p2 = __expf(s[ii][2] - mnew);
            float p3 = __expf(s[ii][3] - mnew);
            float rsum = p0 + p1 + p2 + p3;
#pragma unroll
            for (int off = 8; off >= 1; off >>= 1)
                rsum += __shfl_xor_sync(0xffffffffu, rsum, off, 16);
            l_i[ii] = l_i[ii] * alpha + rsum;
            m_i[ii] = mnew;
#pragma unroll
            for (int cc = 0; cc < 4; cc++) o[ii][cc] *= alpha;
            float4 pv = make_float4(p0, p1, p2, p3);
            *(float4*)&Ps[(r0 + ii) * SMS + c0o] = pv;
        }
        __syncthreads();

        // O += P @ V
        for (int j = 0; j < 64; j += 4) {
            float4 pr[4], vv[4];
#pragma unroll
            for (int ii = 0; ii < 4; ii++)
                pr[ii] = *(const float4*)&Ps[(r0 + ii) * SMS + j];
#pragma unroll
            for (int dj = 0; dj < 4; dj++)
                vv[dj] = *(const float4*)&Vs[(j + dj) * SMS + c0o];
            const float* pf = (const float*)pr;
            const float* vf = (const float*)vv;
#pragma unroll
            for (int ii = 0; ii < 4; ii++)
#pragma unroll
                for (int dj = 0; dj < 4; dj++) {
                    float p = pf[ii * 4 + dj];
#pragma unroll
                    for (int cc = 0; cc < 4; cc++)
                        o[ii][cc] = fmaf(p, vf[dj * 4 + cc], o[ii][cc]);
                }
        }
    }

    // write normalized output into [t][h*64+c]
#pragma unroll
    for (int ii = 0; ii < 4; ii++) {
        float inv_l = 1.0f / l_i[ii];
        size_t base = (size_t)(qi * 64 + r0 + ii) * D_MODEL + h * CH + c0o;
#pragma unroll
        for (int cc = 0; cc < 4; cc++)
            g_att[base + cc] = o[ii][cc] * inv_l;
    }
}

// ---------------- Output projection GEMM ------------------------------------
// out[m][n] = sum_k att[m][k] * Wproj[n][k];  M=4096, N=1024, K=1024
__global__ __launch_bounds__(256) void proj_gemm(
    const float* __restrict__ B, float* __restrict__ out) {
    __shared__ float As[8][128];
    __shared__ float Bs[8][128];
    int tid = threadIdx.x;
    int bm = blockIdx.y, bn = blockIdx.x;
    int tr = tid >> 4, tc = tid & 15;
    int lr = tid >> 1, lk = (tid & 1) * 4;

    const float* Ap = g_att + (size_t)(bm * 128 + lr) * D_MODEL + lk;
    const float* Bp = B + (size_t)(bn * 128 + lr) * D_MODEL + lk;

    float acc[8][8];
#pragma unroll
    for (int i = 0; i < 8; i++)
#pragma unroll
        for (int j = 0; j < 8; j++) acc[i][j] = 0.f;

    for (int k0 = 0; k0 < D_MODEL; k0 += 8) {
        float4 a = *(const float4*)(Ap + k0);
        float4 b = *(const float4*)(Bp + k0);
        As[lk + 0][lr] = a.x; As[lk + 1][lr] = a.y;
        As[lk + 2][lr] = a.z; As[lk + 3][lr] = a.w;
        Bs[lk + 0][lr] = b.x; Bs[lk + 1][lr] = b.y;
        Bs[lk + 2][lr] = b.z; Bs[lk + 3][lr] = b.w;
        __syncthreads();
#pragma unroll
        for (int kk = 0; kk < 8; kk++) {
            float ar[8], br[8];
            *(float4*)&ar[0] = *(const float4*)&As[kk][tr * 8];
            *(float4*)&ar[4] = *(const float4*)&As[kk][tr * 8 + 4];
            *(float4*)&br[0] = *(const float4*)&Bs[kk][tc * 8];
            *(float4*)&br[4] = *(const float4*)&Bs[kk][tc * 8 + 4];
#pragma unroll
            for (int i = 0; i < 8; i++)
#pragma unroll
                for (int j = 0; j < 8; j++)
                    acc[i][j] = fmaf(ar[i], br[j], acc[i][j]);
        }
        __syncthreads();
    }

    int m0 = bm * 128 + tr * 8;
    int n0 = bn * 128 + tc * 8;
#pragma unroll
    for (int i = 0; i < 8; i++)
#pragma unroll
        for (int j = 0; j < 8; j++)
            out[(size_t)(m0 + i) * D_MODEL + n0 + j] = acc[i][j];
}

// ---------------- launch -----------------------------------------------------
extern "C" void kernel_launch(void* const* d_in, const int* in_sizes, int n_in,
                              void* d_out, int out_size) {
    const float* x     = (const float*)d_in[0];
    const float* Wqkv  = (const float*)d_in[1];
    const float* Wproj = (const float*)d_in[2];
    float* out = (float*)d_out;

    cudaFuncSetAttribute(flash_kernel,
                         cudaFuncAttributeMaxDynamicSharedMemorySize, FLASH_SMEM);

    rope_table_kernel<<<T_SEQ, 32>>>();
    qkv_rope_gemm<<<dim3(3 * D_MODEL / 128, T_SEQ / 128), 256>>>(x, Wqkv);
    flash_kernel<<<dim3(64, NH), 256, FLASH_SMEM>>>();
    proj_gemm<<<dim3(D_MODEL / 128, T_SEQ / 128), 256>>>(Wproj, out);
}

// round 2
// speedup vs baseline: 1.1150x; 1.1150x over previous
#include <cuda_runtime.h>
#include <math.h>

#define T_SEQ  4096
#define D_MODEL 1024
#define NH      16
#define CH      64

// ---------------- scratch (device globals; no allocation allowed) ----------
__device__ float g_Q[NH * T_SEQ * CH];     // [h][t][c], rope applied
__device__ float g_K[NH * T_SEQ * CH];     // [h][t][c], rope applied
__device__ float g_V[NH * T_SEQ * CH];     // [h][t][c]
__device__ float g_att[T_SEQ * D_MODEL];   // [t][h*64+c]
__device__ float g_sin[T_SEQ * 32];
__device__ float g_cos[T_SEQ * 32];

// ---------------- RoPE sin/cos table ---------------------------------------
__global__ void rope_table_kernel() {
    int t = blockIdx.x;
    int p = threadIdx.x;                       // pair index 0..31
    double inv = pow(10000.0, -(double)(2 * p) / 64.0);
    float ang = (float)t * (float)inv;
    float s, c;
    sincosf(ang, &s, &c);
    g_sin[t * 32 + p] = s;
    g_cos[t * 32 + p] = c;
}

// ---------------- tf32 helpers ----------------------------------------------
__device__ __forceinline__ unsigned f2tf32(float x) {
    unsigned r;
    asm("cvt.rna.tf32.f32 %0, %1;" : "=r"(r) : "f"(x));
    return r;
}

__device__ __forceinline__ void mma_tf32(float* d, const unsigned* a, const unsigned* b) {
    asm volatile(
        "mma.sync.aligned.m16n8k8.row.col.f32.tf32.tf32.f32 "
        "{%0,%1,%2,%3},{%4,%5,%6,%7},{%8,%9},{%0,%1,%2,%3};"
        : "+f"(d[0]), "+f"(d[1]), "+f"(d[2]), "+f"(d[3])
        : "r"(a[0]), "r"(a[1]), "r"(a[2]), "r"(a[3]), "r"(b[0]), "r"(b[1]));
}

__device__ __forceinline__ void split4(float4 v, unsigned* hp, unsigned* lp) {
    unsigned h0 = f2tf32(v.x), h1 = f2tf32(v.y), h2 = f2tf32(v.z), h3 = f2tf32(v.w);
    *(uint4*)hp = make_uint4(h0, h1, h2, h3);
    unsigned l0 = f2tf32(v.x - __uint_as_float(h0));
    unsigned l1 = f2tf32(v.y - __uint_as_float(h1));
    unsigned l2 = f2tf32(v.z - __uint_as_float(h2));
    unsigned l3 = f2tf32(v.w - __uint_as_float(h3));
    *(uint4*)lp = make_uint4(l0, l1, l2, l3);
}

// ---------------- tf32 GEMM: C = A(row) * B(row as N x K)^T -----------------
// EPI=0: qkv (+rope scatter into g_Q/g_K/g_V), EPI=1: proj -> out
#define SK 20   // smem k-stride (16 used + 4 pad): conflict-free fragment LDS

template<int EPI>
__global__ __launch_bounds__(256) void gemm_tf32(
    const float* __restrict__ Ain, const float* __restrict__ B,
    float* __restrict__ out) {
    __shared__ unsigned Ah[128][SK], Al[128][SK], Bh[128][SK], Bl[128][SK];

    const float* A = (EPI == 1) ? g_att : Ain;

    int tid  = threadIdx.x;
    int lane = tid & 31;
    int warp = tid >> 5;
    int bm = blockIdx.y, bn = blockIdx.x;
    int warp_m = (warp >> 2) * 64;
    int warp_n = (warp & 3) * 32;
    int g  = lane >> 2;       // group id
    int tc = lane & 3;        // thread-in-group

    // gmem load coords: rows r, r+64; k4 = 4-float chunk within 16-wide slice
    int r  = tid >> 2;
    int k4 = (tid & 3) * 4;
    const float* Ap0 = A + (size_t)(bm * 128 + r)      * D_MODEL + k4;
    const float* Ap1 = A + (size_t)(bm * 128 + r + 64) * D_MODEL + k4;
    const float* Bp0 = B + (size_t)(bn * 128 + r)      * D_MODEL + k4;
    const float* Bp1 = B + (size_t)(bn * 128 + r + 64) * D_MODEL + k4;

    float acc[4][4][4];
#pragma unroll
    for (int mt = 0; mt < 4; mt++)
#pragma unroll
        for (int nt = 0; nt < 4; nt++)
#pragma unroll
            for (int i = 0; i < 4; i++) acc[mt][nt][i] = 0.f;

    float4 sa0 = *(const float4*)(Ap0);
    float4 sa1 = *(const float4*)(Ap1);
    float4 sb0 = *(const float4*)(Bp0);
    float4 sb1 = *(const float4*)(Bp1);

    for (int k0 = 0; k0 < D_MODEL; k0 += 16) {
        __syncthreads();
        split4(sa0, &Ah[r][k4],      &Al[r][k4]);
        split4(sa1, &Ah[r + 64][k4], &Al[r + 64][k4]);
        split4(sb0, &Bh[r][k4],      &Bl[r][k4]);
        split4(sb1, &Bh[r + 64][k4], &Bl[r + 64][k4]);
        __syncthreads();
        if (k0 + 16 < D_MODEL) {
            sa0 = *(const float4*)(Ap0 + k0 + 16);
            sa1 = *(const float4*)(Ap1 + k0 + 16);
            sb0 = *(const float4*)(Bp0 + k0 + 16);
            sb1 = *(const float4*)(Bp1 + k0 + 16);
        }
#pragma unroll
        for (int kk = 0; kk < 16; kk += 8) {
            unsigned afh[4][4], afl[4][4], bfh[4][2], bfl[4][2];
#pragma unroll
            for (int mt = 0; mt < 4; mt++) {
                int row = warp_m + mt * 16 + g;
                afh[mt][0] = Ah[row][kk + tc];
                afh[mt][1] = Ah[row + 8][kk + tc];
                afh[mt][2] = Ah[row][kk + tc + 4];
                afh[mt][3] = Ah[row + 8][kk + tc + 4];
                afl[mt][0] = Al[row][kk + tc];
                afl[mt][1] = Al[row + 8][kk + tc];
                afl[mt][2] = Al[row][kk + tc + 4];
                afl[mt][3] = Al[row + 8][kk + tc + 4];
            }
#pragma unroll
            for (int nt = 0; nt < 4; nt++) {
                int col = warp_n + nt * 8 + g;
                bfh[nt][0] = Bh[col][kk + tc];
                bfh[nt][1] = Bh[col][kk + tc + 4];
                bfl[nt][0] = Bl[col][kk + tc];
                bfl[nt][1] = Bl[col][kk + tc + 4];
            }
#pragma unroll
            for (int mt = 0; mt < 4; mt++)
#pragma unroll
                for (int nt = 0; nt < 4; nt++) {
                    mma_tf32(acc[mt][nt], afh[mt], bfh[nt]);
                    mma_tf32(acc[mt][nt], afh[mt], bfl[nt]);
                    mma_tf32(acc[mt][nt], afl[mt], bfh[nt]);
                }
        }
    }

    // ---- epilogue ----
    if (EPI == 0) {
        int mat = (bn * 128) >> 10;                 // 0=q,1=k,2=v
        float* dst = (mat == 0) ? g_Q : (mat == 1 ? g_K : g_V);
#pragma unroll
        for (int mt = 0; mt < 4; mt++)
#pragma unroll
            for (int nt = 0; nt < 4; nt++) {
                int colb = bn * 128 + warp_n + nt * 8 + 2 * tc;
                int cm = colb & 1023;
                int h = cm >> 6, cc = cm & 63, p = cc >> 1;
#pragma unroll
                for (int half = 0; half < 2; half++) {
                    int row = bm * 128 + warp_m + mt * 16 + g + half * 8;
                    float e = acc[mt][nt][half * 2 + 0];
                    float o = acc[mt][nt][half * 2 + 1];
                    size_t idx = ((size_t)h * T_SEQ + row) * CH + cc;
                    if (mat == 2) {
                        *(float2*)&dst[idx] = make_float2(e, o);
                    } else {
                        float sn = g_sin[row * 32 + p];
                        float cs = g_cos[row * 32 + p];
                        *(float2*)&dst[idx] =
                            make_float2(e * cs - o * sn, o * cs + e * sn);
                    }
                }
            }
    } else {
#pragma unroll
        for (int mt = 0; mt < 4; mt++)
#pragma unroll
            for (int nt = 0; nt < 4; nt++) {
                int colb = bn * 128 + warp_n + nt * 8 + 2 * tc;
#pragma unroll
                for (int half = 0; half < 2; half++) {
                    int row = bm * 128 + warp_m + mt * 16 + g + half * 8;
                    *(float2*)&out[(size_t)row * D_MODEL + colb] =
                        make_float2(acc[mt][nt][half * 2 + 0],
                                    acc[mt][nt][half * 2 + 1]);
                }
            }
    }
}

// ---------------- Flash attention (fp32, online softmax) -------------------
#define SMS 68                                  // padded smem row stride
#define FLASH_SMEM (4 * 64 * SMS * 4)

__global__ __launch_bounds__(256) void flash_kernel() {
    extern __shared__ float sm[];
    float* Qs  = sm;                  // [r][c]  64 x SMS
    float* Kts = sm + 64 * SMS;       // [c][j]  (K transposed)
    float* Vs  = sm + 2 * 64 * SMS;   // [j][c]
    float* Ps  = sm + 3 * 64 * SMS;   // [r][j]

    int h  = blockIdx.y;
    int qi = 63 - blockIdx.x;         // heavy tiles first
    int tid = threadIdx.x;
    int ty = tid >> 4, tx = tid & 15;
    int r0 = ty * 4, c0o = tx * 4;

    const float* Qg = g_Q + (size_t)h * T_SEQ * CH;
    const float* Kg = g_K + (size_t)h * T_SEQ * CH;
    const float* Vg = g_V + (size_t)h * T_SEQ * CH;

    // load Q tile
    for (int i = tid; i < 64 * 16; i += 256) {
        int r = i >> 4, c4 = (i & 15) * 4;
        float4 q = *(const float4*)(Qg + (size_t)(qi * 64 + r) * 64 + c4);
        Qs[r * SMS + c4 + 0] = q.x; Qs[r * SMS + c4 + 1] = q.y;
        Qs[r * SMS + c4 + 2] = q.z; Qs[r * SMS + c4 + 3] = q.w;
    }

    float m_i[4], l_i[4], o[4][4];
#pragma unroll
    for (int ii = 0; ii < 4; ii++) {
        m_i[ii] = -1e30f; l_i[ii] = 0.f;
#pragma unroll
        for (int cc = 0; cc < 4; cc++) o[ii][cc] = 0.f;
    }

    for (int kt = 0; kt <= qi; kt++) {
        __syncthreads();   // prev PV reads done (also covers Q load on iter 0)
        // load K (transposed) and V tiles
        for (int i = tid; i < 64 * 16; i += 256) {
            int r = i >> 4, c4 = (i & 15) * 4;
            float4 kk = *(const float4*)(Kg + (size_t)(kt * 64 + r) * 64 + c4);
            Kts[(c4 + 0) * SMS + r] = kk.x; Kts[(c4 + 1) * SMS + r] = kk.y;
            Kts[(c4 + 2) * SMS + r] = kk.z; Kts[(c4 + 3) * SMS + r] = kk.w;
            float4 vv = *(const float4*)(Vg + (size_t)(kt * 64 + r) * 64 + c4);
            Vs[r * SMS + c4 + 0] = vv.x; Vs[r * SMS + c4 + 1] = vv.y;
            Vs[r * SMS + c4 + 2] = vv.z; Vs[r * SMS + c4 + 3] = vv.w;
        }
        __syncthreads();

        // S = Q K^T for this thread's 4x4
        float s[4][4];
#pragma unroll
        for (int ii = 0; ii < 4; ii++)
#pragma unroll
            for (int jj = 0; jj < 4; jj++) s[ii][jj] = 0.f;

        for (int c = 0; c < 64; c += 4) {
            float4 qv[4], kv[4];
#pragma unroll
            for (int ii = 0; ii < 4; ii++)
                qv[ii] = *(const float4*)&Qs[(r0 + ii) * SMS + c];
#pragma unroll
            for (int cc = 0; cc < 4; cc++)
                kv[cc] = *(const float4*)&Kts[(c + cc) * SMS + c0o];
            const float* qf = (const float*)qv;
            const float* kf = (const float*)kv;
#pragma unroll
            for (int ii = 0; ii < 4; ii++)
#pragma unroll
                for (int cc = 0; cc < 4; cc++) {
                    float q = qf[ii * 4 + cc];
#pragma unroll
                    for (int jj = 0; jj < 4; jj++)
                        s[ii][jj] = fmaf(q, kf[cc * 4 + jj], s[ii][jj]);
                }
        }

        bool diag = (kt == qi);
#pragma unroll
        for (int ii = 0; ii < 4; ii++)
#pragma unroll
            for (int jj = 0; jj < 4; jj++) {
                float v = s[ii][jj] * 0.125f;   // 1/sqrt(64)
                if (diag && (c0o + jj > r0 + ii)) v = -1e30f;
                s[ii][jj] = v;
            }

        // online softmax per row (16 lanes share a row)
#pragma unroll
        for (int ii = 0; ii < 4; ii++) {
            float rmax = fmaxf(fmaxf(s[ii][0], s[ii][1]), fmaxf(s[ii][2], s[ii][3]));
#pragma unroll
            for (int off = 8; off >= 1; off >>= 1)
                rmax = fmaxf(rmax, __shfl_xor_sync(0xffffffffu, rmax, off, 16));
            float mnew = fmaxf(m_i[ii], rmax);
            float alpha = __expf(m_i[ii] - mnew);
            float p0 = __expf(s[ii][0] - mnew);
            float p1 = __expf(s[ii][1] - mnew);
            float p2 = __expf(s[ii][2] - mnew);
            float p3 = __expf(s[ii][3] - mnew);
            float rsum = p0 + p1 + p2 + p3;
#pragma unroll
            for (int off = 8; off >= 1; off >>= 1)
                rsum += __shfl_xor_sync(0xffffffffu, rsum, off, 16);
            l_i[ii] = l_i[ii] * alpha + rsum;
            m_i[ii] = mnew;
#pragma unroll
            for (int cc = 0; cc < 4; cc++) o[ii][cc] *= alpha;
            float4 pv = make_float4(p0, p1, p2, p3);
            *(float4*)&Ps[(r0 + ii) * SMS + c0o] = pv;
        }
        __syncthreads();

        // O += P @ V
        for (int j = 0; j < 64; j += 4) {
            float4 pr[4], vv[4];
#pragma unroll
            for (int ii = 0; ii < 4; ii++)
                pr[ii] = *(const float4*)&Ps[(r0 + ii) * SMS + j];
#pragma unroll
            for (int dj = 0; dj < 4; dj++)
                vv[dj] = *(const float4*)&Vs[(j + dj) * SMS + c0o];
            const float* pf = (const float*)pr;
            const float* vf = (const float*)vv;
#pragma unroll
            for (int ii = 0; ii < 4; ii++)
#pragma unroll
                for (int dj = 0; dj < 4; dj++) {
                    float p = pf[ii * 4 + dj];
#pragma unroll
                    for (int cc = 0; cc < 4; cc++)
                        o[ii][cc] = fmaf(p, vf[dj * 4 + cc], o[ii][cc]);
                }
        }
    }

    // write normalized output into [t][h*64+c]
#pragma unroll
    for (int ii = 0; ii < 4; ii++) {
        float inv_l = 1.0f / l_i[ii];
        size_t base = (size_t)(qi * 64 + r0 + ii) * D_MODEL + h * CH + c0o;
#pragma unroll
        for (int cc = 0; cc < 4; cc++)
            g_att[base + cc] = o[ii][cc] * inv_l;
    }
}

// ---------------- launch -----------------------------------------------------
extern "C" void kernel_launch(void* const* d_in, const int* in_sizes, int n_in,
                              void* d_out, int out_size) {
    const float* x     = (const float*)d_in[0];
    const float* Wqkv  = (const float*)d_in[1];
    const float* Wproj = (const float*)d_in[2];
    float* out = (float*)d_out;

    cudaFuncSetAttribute(flash_kernel,
                         cudaFuncAttributeMaxDynamicSharedMemorySize, FLASH_SMEM);

    rope_table_kernel<<<T_SEQ, 32>>>();
    gemm_tf32<0><<<dim3(3 * D_MODEL / 128, T_SEQ / 128), 256>>>(x, Wqkv, nullptr);
    flash_kernel<<<dim3(64, NH), 256, FLASH_SMEM>>>();
    gemm_tf32<1><<<dim3(D_MODEL / 128, T_SEQ / 128), 256>>>(nullptr, Wproj, out);
}